// round 1
// baseline (speedup 1.0000x reference)
#include <cuda_runtime.h>
#include <math.h>
#include <stdint.h>

#define BATCH 32768
#define FDIM 512
#define HS 256
#define UU 512
#define OUTD 128
#define STEPS 5
#define EPSBN 1e-5f

// ---------------- scratch (device globals; no allocation) ----------------
__device__ float g_feats[BATCH * FDIM];   // bn0(features)
__device__ float g_h0[BATCH * HS];        // transformer ping
__device__ float g_h1[BATCH * HS];        // transformer pong (x)
__device__ float g_z[BATCH * FDIM];       // att*prior pre-sparsemax
__device__ float g_prior[BATCH * FDIM];
__device__ float g_acc[BATCH * OUTD];     // sum of relu(x[:, :128])

// ---------------- init: bn0 + prior=1 + acc=0 ----------------
__global__ void k_init(const float* __restrict__ feat,
                       const float* __restrict__ g, const float* __restrict__ b,
                       const float* __restrict__ m, const float* __restrict__ v)
{
    int i = blockIdx.x * blockDim.x + threadIdx.x;
    if (i < BATCH * FDIM) {
        int c = i & (FDIM - 1);
        g_feats[i] = g[c] * (feat[i] - m[c]) * rsqrtf(v[c] + EPSBN) + b[c];
        g_prior[i] = 1.0f;
        if (i < BATCH * OUTD) g_acc[i] = 0.0f;
    }
}

// ---------------- GLU FeatureBlock GEMM ----------------
// C[i,j] = (res? res[i,j]*sqrt(.5) : 0) + bnA(sum_k A'[i,k]W[k,j]) * sigmoid(bnB(sum_k A'[i,k]W[k,j+256]))
// A' = A elementwise * mask (if mask != null). A:[B,K], W:[K,512] row-major, C:[B,256].
// If accOut: accOut[i,j] += relu(C[i,j]) for j<128.
// Tile: BM=128, BN=64 (of the 256 GLU cols), BK=16, 256 threads, 8x(4+4) per thread.
template<int K>
__global__ __launch_bounds__(256)
void k_glu(const float* __restrict__ A, const float* __restrict__ mask,
           const float* __restrict__ W,
           const float* __restrict__ bg, const float* __restrict__ bb,
           const float* __restrict__ bm, const float* __restrict__ bv,
           const float* __restrict__ res,
           float* __restrict__ C, float* __restrict__ accOut)
{
    __shared__ float As[16][128];
    __shared__ float Wa[16][64];
    __shared__ float Wb[16][64];

    const int tid = threadIdx.x;
    const int ty = tid >> 4;          // 0..15 -> row group of 8
    const int tx = tid & 15;          // 0..15 -> col group of 4
    const int row0 = blockIdx.y * 128;
    const int col0 = blockIdx.x * 64;

    float acc_a[8][4], acc_b[8][4];
#pragma unroll
    for (int r = 0; r < 8; r++)
#pragma unroll
        for (int c = 0; c < 4; c++) { acc_a[r][c] = 0.f; acc_b[r][c] = 0.f; }

    const int wr = tid >> 4;          // W k-row within tile
    const int wc = (tid & 15) * 4;    // W col within 64

    for (int kt = 0; kt < K; kt += 16) {
        // A tile: 128 rows x 16 k = 512 float4, 2 per thread. Stored transposed As[k][row].
#pragma unroll
        for (int l = 0; l < 2; l++) {
            int li = tid * 2 + l;
            int r  = li >> 2;
            int kq = (li & 3) * 4;
            float4 av = *(const float4*)(A + (size_t)(row0 + r) * K + kt + kq);
            if (mask) {
                float4 mv = *(const float4*)(mask + (size_t)(row0 + r) * K + kt + kq);
                av.x *= mv.x; av.y *= mv.y; av.z *= mv.z; av.w *= mv.w;
            }
            As[kq + 0][r] = av.x; As[kq + 1][r] = av.y;
            As[kq + 2][r] = av.z; As[kq + 3][r] = av.w;
        }
        // W tiles (both GLU halves)
        {
            const float* wrow = W + (size_t)(kt + wr) * UU;
            *(float4*)&Wa[wr][wc] = *(const float4*)(wrow + col0 + wc);
            *(float4*)&Wb[wr][wc] = *(const float4*)(wrow + col0 + 256 + wc);
        }
        __syncthreads();
#pragma unroll
        for (int kk = 0; kk < 16; kk++) {
            float a[8];
            float4 a0 = *(float4*)&As[kk][ty * 8];
            float4 a1 = *(float4*)&As[kk][ty * 8 + 4];
            a[0] = a0.x; a[1] = a0.y; a[2] = a0.z; a[3] = a0.w;
            a[4] = a1.x; a[5] = a1.y; a[6] = a1.z; a[7] = a1.w;
            float4 w0 = *(float4*)&Wa[kk][tx * 4];
            float4 w1 = *(float4*)&Wb[kk][tx * 4];
            float wa[4] = {w0.x, w0.y, w0.z, w0.w};
            float wb[4] = {w1.x, w1.y, w1.z, w1.w};
#pragma unroll
            for (int r = 0; r < 8; r++)
#pragma unroll
                for (int c = 0; c < 4; c++) {
                    acc_a[r][c] += a[r] * wa[c];
                    acc_b[r][c] += a[r] * wb[c];
                }
        }
        __syncthreads();
    }

    // epilogue: bn + GLU + residual (+ relu accumulate)
    float ga[4], bba[4], ma[4], va[4], gb[4], bbb[4], mb[4], vb[4];
#pragma unroll
    for (int c = 0; c < 4; c++) {
        int ja = col0 + tx * 4 + c;
        int jb = ja + 256;
        ga[c] = bg[ja]; bba[c] = bb[ja]; ma[c] = bm[ja]; va[c] = rsqrtf(bv[ja] + EPSBN);
        gb[c] = bg[jb]; bbb[c] = bb[jb]; mb[c] = bm[jb]; vb[c] = rsqrtf(bv[jb] + EPSBN);
    }
#pragma unroll
    for (int r = 0; r < 8; r++) {
        int gr = row0 + ty * 8 + r;
#pragma unroll
        for (int c = 0; c < 4; c++) {
            int gc = col0 + tx * 4 + c;
            float xa = ga[c] * (acc_a[r][c] - ma[c]) * va[c] + bba[c];
            float xb = gb[c] * (acc_b[r][c] - mb[c]) * vb[c] + bbb[c];
            float o = xa * (1.0f / (1.0f + __expf(-xb)));
            if (res) o += res[(size_t)gr * HS + gc] * 0.70710678118654752f;
            C[(size_t)gr * HS + gc] = o;
            if (accOut && gc < OUTD)
                accOut[(size_t)gr * OUTD + gc] += fmaxf(o, 0.0f);
        }
    }
}

// ---------------- generic small GEMM (attention / final) ----------------
// ATT=true : out[i,j] = bn(acc; g,b,m,v at col j) * prior[i*ldp + j]   (z pre-sparsemax)
// ATT=false: out[i,j] = acc + bias[j]
template<bool ATT>
__global__ __launch_bounds__(256)
void k_gemm(const float* __restrict__ A, int lda, int aoff, int K,
            const float* __restrict__ W, int ldw,
            const float* __restrict__ g, const float* __restrict__ b,
            const float* __restrict__ m, const float* __restrict__ v,
            const float* __restrict__ prior, int ldp,
            const float* __restrict__ bias,
            float* __restrict__ Cout, int ldc)
{
    __shared__ float As[16][128];
    __shared__ float Ws[16][64];

    const int tid = threadIdx.x;
    const int ty = tid >> 4;
    const int tx = tid & 15;
    const int row0 = blockIdx.y * 128;
    const int col0 = blockIdx.x * 64;

    float acc[8][4];
#pragma unroll
    for (int r = 0; r < 8; r++)
#pragma unroll
        for (int c = 0; c < 4; c++) acc[r][c] = 0.f;

    const int wr = tid >> 4;
    const int wc = (tid & 15) * 4;

    for (int kt = 0; kt < K; kt += 16) {
#pragma unroll
        for (int l = 0; l < 2; l++) {
            int li = tid * 2 + l;
            int r  = li >> 2;
            int kq = (li & 3) * 4;
            float4 av = *(const float4*)(A + (size_t)(row0 + r) * lda + aoff + kt + kq);
            As[kq + 0][r] = av.x; As[kq + 1][r] = av.y;
            As[kq + 2][r] = av.z; As[kq + 3][r] = av.w;
        }
        *(float4*)&Ws[wr][wc] = *(const float4*)(W + (size_t)(kt + wr) * ldw + col0 + wc);
        __syncthreads();
#pragma unroll
        for (int kk = 0; kk < 16; kk++) {
            float a[8];
            float4 a0 = *(float4*)&As[kk][ty * 8];
            float4 a1 = *(float4*)&As[kk][ty * 8 + 4];
            a[0] = a0.x; a[1] = a0.y; a[2] = a0.z; a[3] = a0.w;
            a[4] = a1.x; a[5] = a1.y; a[6] = a1.z; a[7] = a1.w;
            float4 w0 = *(float4*)&Ws[kk][tx * 4];
            float wv[4] = {w0.x, w0.y, w0.z, w0.w};
#pragma unroll
            for (int r = 0; r < 8; r++)
#pragma unroll
                for (int c = 0; c < 4; c++) acc[r][c] += a[r] * wv[c];
        }
        __syncthreads();
    }

#pragma unroll
    for (int r = 0; r < 8; r++) {
        int gr = row0 + ty * 8 + r;
#pragma unroll
        for (int c = 0; c < 4; c++) {
            int gc = col0 + tx * 4 + c;
            float o = acc[r][c];
            if (ATT) {
                o = g[gc] * (o - m[gc]) * rsqrtf(v[gc] + EPSBN) + b[gc];
                o *= prior[(size_t)gr * ldp + gc];
            } else {
                o += bias[gc];
            }
            Cout[(size_t)gr * ldc + gc] = o;
        }
    }
}

// ---------------- sparsemax (one 512-thread block per row) ----------------
__global__ __launch_bounds__(512)
void k_sparsemax(const float* __restrict__ z, float* __restrict__ prior,
                 float* __restrict__ maskOut)
{
    __shared__ float s[512];    // sorted values
    __shared__ float c1[512];   // scan ping
    __shared__ float c2[512];   // scan pong
    __shared__ int s_k;
    __shared__ float s_tau;

    const int row = blockIdx.x;
    const int tid = threadIdx.x;
    const float zv = z[(size_t)row * 512 + tid];
    s[tid] = zv;
    __syncthreads();

    // bitonic sort, descending
    for (int k = 2; k <= 512; k <<= 1) {
        for (int j = k >> 1; j > 0; j >>= 1) {
            int ixj = tid ^ j;
            if (ixj > tid) {
                float a = s[tid], bb = s[ixj];
                bool seg = ((tid & k) == 0);
                if (seg ? (a < bb) : (a > bb)) { s[tid] = bb; s[ixj] = a; }
            }
            __syncthreads();
        }
    }

    // inclusive scan (Hillis-Steele)
    c1[tid] = s[tid];
    __syncthreads();
    float* src = c1; float* dst = c2;
    for (int off = 1; off < 512; off <<= 1) {
        float val = src[tid];
        if (tid >= off) val += src[tid - off];
        dst[tid] = val;
        __syncthreads();
        float* t = src; src = dst; dst = t;
    }

    const float cum = src[tid];
    const float zs = s[tid];
    int sup = (1.0f + (float)(tid + 1) * zs > cum) ? 1 : 0;
    if (tid == 0) s_k = 0;
    __syncthreads();
    unsigned bal = __ballot_sync(0xffffffffu, sup);
    if ((tid & 31) == 0) atomicAdd(&s_k, __popc(bal));
    __syncthreads();
    const int kz = s_k;
    if (tid == 0) s_tau = (src[kz - 1] - 1.0f) / (float)kz;
    __syncthreads();

    const float mk = fmaxf(zv - s_tau, 0.0f);
    maskOut[(size_t)row * 512 + tid] = mk;
    prior[(size_t)row * 512 + tid] *= (1.5f - mk);
}

// ---------------- launch ----------------
extern "C" void kernel_launch(void* const* d_in, const int* in_sizes, int n_in,
                              void* d_out, int out_size)
{
    const float* features = (const float*)d_in[0];
    const float* bn0_g = (const float*)d_in[1];
    const float* bn0_b = (const float*)d_in[2];
    const float* bn0_m = (const float*)d_in[3];
    const float* bn0_v = (const float*)d_in[4];
    const float* Ws0   = (const float*)d_in[5];   // [512,512]
    const float* Ws1   = (const float*)d_in[6];   // [256,512]
    const float* Wu    = (const float*)d_in[7];   // [6,2,256,512]
    const float* ft_g  = (const float*)d_in[8];   // [6,4,512]
    const float* ft_b  = (const float*)d_in[9];
    const float* ft_m  = (const float*)d_in[10];
    const float* ft_v  = (const float*)d_in[11];
    const float* W_att = (const float*)d_in[12];  // [5,128,512]
    const float* att_g = (const float*)d_in[13];  // [5,512]
    const float* att_b = (const float*)d_in[14];
    const float* att_m = (const float*)d_in[15];
    const float* att_v = (const float*)d_in[16];
    const float* Wf    = (const float*)d_in[17];  // [128,128]
    const float* bf    = (const float*)d_in[18];  // [128]

    float *feats, *h0, *h1, *z, *prior, *acc;
    cudaGetSymbolAddress((void**)&feats, g_feats);
    cudaGetSymbolAddress((void**)&h0, g_h0);
    cudaGetSymbolAddress((void**)&h1, g_h1);
    cudaGetSymbolAddress((void**)&z, g_z);
    cudaGetSymbolAddress((void**)&prior, g_prior);
    cudaGetSymbolAddress((void**)&acc, g_acc);

    float* outF  = (float*)d_out;                       // final [B,128]
    float* masks = outF + (size_t)BATCH * OUTD;         // masks [5,B,512]

    k_init<<<(BATCH * FDIM) / 256, 256>>>(features, bn0_g, bn0_b, bn0_m, bn0_v);

    const dim3 gGlu(4, BATCH / 128);   // 256 GLU cols / 64, B/128

    auto ft = [&](const float* maskp, int t, float* accOut) {
        const float* Wt = Wu + (size_t)t * 2 * HS * UU;
        const float* fg = ft_g + (size_t)t * 4 * UU;
        const float* fb = ft_b + (size_t)t * 4 * UU;
        const float* fm = ft_m + (size_t)t * 4 * UU;
        const float* fv = ft_v + (size_t)t * 4 * UU;
        k_glu<512><<<gGlu, 256>>>(feats, maskp, Ws0,
                                  fg, fb, fm, fv, nullptr, h0, nullptr);
        k_glu<256><<<gGlu, 256>>>(h0, nullptr, Ws1,
                                  fg + UU, fb + UU, fm + UU, fv + UU, h0, h1, nullptr);
        k_glu<256><<<gGlu, 256>>>(h1, nullptr, Wt,
                                  fg + 2 * UU, fb + 2 * UU, fm + 2 * UU, fv + 2 * UU, h1, h0, nullptr);
        k_glu<256><<<gGlu, 256>>>(h0, nullptr, Wt + (size_t)HS * UU,
                                  fg + 3 * UU, fb + 3 * UU, fm + 3 * UU, fv + 3 * UU, h0, h1, accOut);
    };

    ft(nullptr, 0, nullptr);

    for (int s = 0; s < STEPS; s++) {
        const dim3 gAtt(FDIM / 64, BATCH / 128);
        k_gemm<true><<<gAtt, 256>>>(h1, HS, OUTD, 128,
                                    W_att + (size_t)s * 128 * FDIM, FDIM,
                                    att_g + (size_t)s * FDIM, att_b + (size_t)s * FDIM,
                                    att_m + (size_t)s * FDIM, att_v + (size_t)s * FDIM,
                                    prior, FDIM, nullptr,
                                    z, FDIM);
        k_sparsemax<<<BATCH, 512>>>(z, prior, masks + (size_t)s * BATCH * FDIM);
        ft(masks + (size_t)s * BATCH * FDIM, s + 1, acc);
    }

    const dim3 gFin(OUTD / 64, BATCH / 128);
    k_gemm<false><<<gFin, 256>>>(acc, OUTD, 0, 128,
                                 Wf, OUTD,
                                 nullptr, nullptr, nullptr, nullptr,
                                 nullptr, 0, bf,
                                 outF, OUTD);
}

// round 3
// speedup vs baseline: 2.0168x; 2.0168x over previous
#include <cuda_runtime.h>
#include <cuda_bf16.h>
#include <math.h>
#include <stdint.h>

#define BATCH 32768
#define FDIM 512
#define HS 256
#define UU 512
#define OUTD 128
#define STEPS 5
#define EPSBN 1e-5f

typedef __nv_bfloat16 bf16;

// ---------------- scratch (device globals; no allocation) ----------------
__device__ float g_feats[BATCH * FDIM];
__device__ bf16  g_Ah[BATCH * FDIM];     // block-0 GEMM operand (feats or mask*feats), hi
__device__ bf16  g_Al[BATCH * FDIM];     // lo
__device__ bf16  g_h0h[BATCH * HS], g_h0l[BATCH * HS];
__device__ bf16  g_h1h[BATCH * HS], g_h1l[BATCH * HS];
__device__ float g_z[BATCH * FDIM];
__device__ float g_prior[BATCH * FDIM];
__device__ float g_acc[BATCH * OUTD];

// prepped weights (transposed to [N,K], bf16 hi/lo; GLU ones N-permuted)
__device__ bf16 g_W0h[512 * 512], g_W0l[512 * 512];
__device__ bf16 g_W1h[512 * 256], g_W1l[512 * 256];
__device__ bf16 g_WUh[12 * 512 * 256], g_WUl[12 * 512 * 256];
__device__ bf16 g_WAh[5 * 512 * 128], g_WAl[5 * 512 * 128];
__device__ float g_fts[6 * 4 * 512], g_ftt[6 * 4 * 512];   // fused bn scale/bias
__device__ float g_as[5 * 512], g_at[5 * 512];

// ---------------- PTX helpers (sm_100-safe: cp.async / ldmatrix / mma.sync) ---
__device__ __forceinline__ uint32_t smem_u32(const void* p) {
    uint32_t a;
    asm("{ .reg .u64 t; cvta.to.shared.u64 t, %1; cvt.u32.u64 %0, t; }" : "=r"(a) : "l"(p));
    return a;
}
__device__ __forceinline__ void cpa16(uint32_t s, const void* g) {
    asm volatile("cp.async.cg.shared.global [%0], [%1], 16;" :: "r"(s), "l"(g));
}
__device__ __forceinline__ void cpa_commit() {
    asm volatile("cp.async.commit_group;" ::: "memory");
}
template<int N>
__device__ __forceinline__ void cpa_wait() {
    asm volatile("cp.async.wait_group %0;" :: "n"(N) : "memory");
}
__device__ __forceinline__ void ldm4(uint32_t* v, uint32_t addr) {
    asm volatile("ldmatrix.sync.aligned.m8n8.x4.shared.b16 {%0,%1,%2,%3}, [%4];"
                 : "=r"(v[0]), "=r"(v[1]), "=r"(v[2]), "=r"(v[3]) : "r"(addr));
}
__device__ __forceinline__ void mma16(float* c, const uint32_t* a, uint32_t b0, uint32_t b1) {
    asm volatile("mma.sync.aligned.m16n8k16.row.col.f32.bf16.bf16.f32 "
                 "{%0,%1,%2,%3}, {%4,%5,%6,%7}, {%8,%9}, {%0,%1,%2,%3};"
                 : "+f"(c[0]), "+f"(c[1]), "+f"(c[2]), "+f"(c[3])
                 : "r"(a[0]), "r"(a[1]), "r"(a[2]), "r"(a[3]), "r"(b0), "r"(b1));
}

// ---------------- prep kernels ----------------
// W [K,512] fp32 -> out [512,K] bf16 hi/lo, GLU column permutation.
__global__ void k_prep_glu(const float* __restrict__ W, int K,
                           bf16* __restrict__ oh, bf16* __restrict__ ol)
{
    int idx = blockIdx.x * 256 + threadIdx.x;
    if (idx >= 512 * K) return;
    int n = idx / K, k = idx - n * K;
    int g = n >> 8, w = n & 255, half = w >> 7, jl = w & 127;
    int col = half ? 256 + g * 128 + jl : g * 128 + jl;
    float v = W[(size_t)k * 512 + col];
    bf16 h = __float2bfloat16(v);
    oh[idx] = h;
    ol[idx] = __float2bfloat16(v - __bfloat162float(h));
}

// W_att [5][128,512] -> [5][512,128] bf16 hi/lo, no perm.
__global__ void k_prep_att(const float* __restrict__ Wa,
                           bf16* __restrict__ oh, bf16* __restrict__ ol)
{
    int idx = blockIdx.x * 256 + threadIdx.x;
    if (idx >= 5 * 512 * 128) return;
    int s = idx / (512 * 128);
    int r = idx - s * 512 * 128;
    int n = r >> 7, k = r & 127;
    float v = Wa[(size_t)s * 128 * 512 + (size_t)k * 512 + n];
    bf16 h = __float2bfloat16(v);
    oh[idx] = h;
    ol[idx] = __float2bfloat16(v - __bfloat162float(h));
}

__global__ void k_prep_bn(const float* __restrict__ fg, const float* __restrict__ fb,
                          const float* __restrict__ fm, const float* __restrict__ fv,
                          const float* __restrict__ ag, const float* __restrict__ ab,
                          const float* __restrict__ am, const float* __restrict__ av)
{
    int idx = blockIdx.x * 256 + threadIdx.x;
    if (idx < 6 * 4 * 512) {
        float s = fg[idx] * rsqrtf(fv[idx] + EPSBN);
        g_fts[idx] = s;
        g_ftt[idx] = fb[idx] - fm[idx] * s;
    }
    if (idx < 5 * 512) {
        float s = ag[idx] * rsqrtf(av[idx] + EPSBN);
        g_as[idx] = s;
        g_at[idx] = ab[idx] - am[idx] * s;
    }
}

__global__ void k_init(const float* __restrict__ feat,
                       const float* __restrict__ g, const float* __restrict__ b,
                       const float* __restrict__ m, const float* __restrict__ v)
{
    int i = blockIdx.x * blockDim.x + threadIdx.x;
    if (i < BATCH * FDIM) {
        int c = i & (FDIM - 1);
        float f = g[c] * (feat[i] - m[c]) * rsqrtf(v[c] + EPSBN) + b[c];
        g_feats[i] = f;
        bf16 h = __float2bfloat16(f);
        g_Ah[i] = h;
        g_Al[i] = __float2bfloat16(f - __bfloat162float(h));
        g_prior[i] = 1.0f;
        if (i < BATCH * OUTD) g_acc[i] = 0.0f;
    }
}

// ---------------- HMMA GEMM: MODE 0 = GLU, MODE 1 = attention ----------------
// D[128,256] = Ah*Bh^T + Ah*Bl^T + Al*Bh^T  (fp32 accum), A [128,K], B rows
// [g*256, g*256+256) of prepped [512/512, K] (both K-major).
// Tile: BM=128, BN=256, BK=64, 8 warps each 16(M)x256(N), 2-stage cp.async.
#define STAGE_BYTES 98304     // Ah 16K | Al 16K | Bh 32K | Bl 32K
#define PARAM_OFF   (2 * STAGE_BYTES)
#define SMEM_TOTAL  (PARAM_OFF + 2048)

template<int MODE>
__global__ __launch_bounds__(256)
void k_mma(const bf16* __restrict__ Ah, const bf16* __restrict__ Al, int lda, int K,
           const bf16* __restrict__ Bh, const bf16* __restrict__ Bl,
           const float* __restrict__ bs, const float* __restrict__ bt,
           const bf16* __restrict__ resh, const bf16* __restrict__ resl,
           bf16* __restrict__ outh, bf16* __restrict__ outl,
           float* __restrict__ accp,
           const float* __restrict__ prior, float* __restrict__ zout)
{
    extern __shared__ __align__(128) char smem[];
    const int tid = threadIdx.x, wid = tid >> 5, lid = tid & 31;
    const int g = blockIdx.x;
    const int row0 = blockIdx.y * 128;
    const uint32_t sb = smem_u32(smem);

    // stage fused-BN params
    {
        float* sE = (float*)(smem + PARAM_OFF);
        float* tE = (float*)(smem + PARAM_OFF + 1024);
        int col;
        if (MODE == 0) col = (tid < 128) ? g * 128 + tid : 256 + g * 128 + (tid - 128);
        else           col = g * 256 + tid;
        sE[tid] = bs[col];
        tE[tid] = bt[col];
    }

    float acc[32][4];
#pragma unroll
    for (int i = 0; i < 32; i++)
#pragma unroll
        for (int j = 0; j < 4; j++) acc[i][j] = 0.0f;

    const int nch = K >> 6;

    auto load_stage = [&](int ch) {
        const int s = ch & 1, kt = ch << 6;
        const uint32_t st = sb + s * STAGE_BYTES;
#pragma unroll
        for (int i = 0; i < 4; i++) {
            int idx = tid + i * 256;
            int r = idx >> 3, c = idx & 7;
            uint32_t so = (uint32_t)(r * 128 + ((c ^ (r & 7)) << 4));
            const bf16* gp = Ah + (size_t)(row0 + r) * lda + kt + c * 8;
            const bf16* gq = Al + (size_t)(row0 + r) * lda + kt + c * 8;
            cpa16(st + so, gp);
            cpa16(st + 16384 + so, gq);
        }
#pragma unroll
        for (int i = 0; i < 8; i++) {
            int idx = tid + i * 256;
            int r = idx >> 3, c = idx & 7;
            uint32_t so = (uint32_t)(r * 128 + ((c ^ (r & 7)) << 4));
            const bf16* gp = Bh + (size_t)(g * 256 + r) * K + kt + c * 8;
            const bf16* gq = Bl + (size_t)(g * 256 + r) * K + kt + c * 8;
            cpa16(st + 32768 + so, gp);
            cpa16(st + 65536 + so, gq);
        }
    };

    load_stage(0);
    cpa_commit();

    const int lr = lid & 15, lc = lid >> 4;

    for (int ch = 0; ch < nch; ch++) {
        if (ch + 1 < nch) { load_stage(ch + 1); cpa_commit(); cpa_wait<1>(); }
        else              { cpa_wait<0>(); }
        __syncthreads();
        const uint32_t st = sb + (ch & 1) * STAGE_BYTES;
#pragma unroll
        for (int ks = 0; ks < 4; ks++) {
            uint32_t ah[4], al[4];
            {
                int r = wid * 16 + lr;
                int cc = 2 * ks + lc;
                uint32_t ad = st + r * 128 + ((cc ^ (r & 7)) << 4);
                ldm4(ah, ad);
                ldm4(al, ad + 16384);
            }
#pragma unroll
            for (int gp = 0; gp < 16; gp++) {
                int r = gp * 16 + lr;
                int cc = 2 * ks + lc;
                uint32_t bd = st + 32768 + r * 128 + ((cc ^ (r & 7)) << 4);
                uint32_t bh[4], bl[4];
                ldm4(bh, bd);
                ldm4(bl, bd + 32768);
                mma16(acc[2 * gp],     ah, bh[0], bh[2]);
                mma16(acc[2 * gp + 1], ah, bh[1], bh[3]);
                mma16(acc[2 * gp],     ah, bl[0], bl[2]);
                mma16(acc[2 * gp + 1], ah, bl[1], bl[3]);
                mma16(acc[2 * gp],     al, bh[0], bh[2]);
                mma16(acc[2 * gp + 1], al, bh[1], bh[3]);
            }
        }
        __syncthreads();
    }

    // ---------------- epilogue (register-resident accums) ----------------
    const float* sE = (const float*)(smem + PARAM_OFF);
    const float* tE = (const float*)(smem + PARAM_OFF + 1024);
    const int gid = lid >> 2, tp = lid & 3;
    const int r0g = row0 + wid * 16 + gid;

    if (MODE == 0) {
#pragma unroll
        for (int nt = 0; nt < 16; nt++) {
            const int cn = nt * 8 + tp * 2;
            const float sa0 = sE[cn], sa1 = sE[cn + 1];
            const float ta0 = tE[cn], ta1 = tE[cn + 1];
            const float sb0 = sE[128 + cn], sb1 = sE[128 + cn + 1];
            const float tb0 = tE[128 + cn], tb1 = tE[128 + cn + 1];
#pragma unroll
            for (int h = 0; h < 2; h++) {
                const int row = r0g + h * 8;
                float xa0 = acc[nt][2 * h] * sa0 + ta0;
                float xa1 = acc[nt][2 * h + 1] * sa1 + ta1;
                float xb0 = acc[nt + 16][2 * h] * sb0 + tb0;
                float xb1 = acc[nt + 16][2 * h + 1] * sb1 + tb1;
                float o0 = xa0 * (1.0f / (1.0f + __expf(-xb0)));
                float o1 = xa1 * (1.0f / (1.0f + __expf(-xb1)));
                const size_t ob = (size_t)row * HS + g * 128 + cn;
                if (resh) {
                    __nv_bfloat162 rh = *(const __nv_bfloat162*)(resh + ob);
                    __nv_bfloat162 rl = *(const __nv_bfloat162*)(resl + ob);
                    o0 = fmaf(__bfloat162float(rh.x) + __bfloat162float(rl.x),
                              0.70710678118654752f, o0);
                    o1 = fmaf(__bfloat162float(rh.y) + __bfloat162float(rl.y),
                              0.70710678118654752f, o1);
                }
                bf16 h0 = __float2bfloat16(o0);
                bf16 h1 = __float2bfloat16(o1);
                __nv_bfloat162 hh; hh.x = h0; hh.y = h1;
                *(__nv_bfloat162*)(outh + ob) = hh;
                __nv_bfloat162 ll;
                ll.x = __float2bfloat16(o0 - __bfloat162float(h0));
                ll.y = __float2bfloat16(o1 - __bfloat162float(h1));
                *(__nv_bfloat162*)(outl + ob) = ll;
                if (accp && g == 0) {
                    float2* ap = (float2*)(accp + (size_t)row * OUTD + cn);
                    float2 av = *ap;
                    av.x += fmaxf(o0, 0.0f);
                    av.y += fmaxf(o1, 0.0f);
                    *ap = av;
                }
            }
        }
    } else {
#pragma unroll
        for (int nt = 0; nt < 32; nt++) {
            const int cn = nt * 8 + tp * 2;
            const float s0 = sE[cn], s1 = sE[cn + 1];
            const float t0 = tE[cn], t1 = tE[cn + 1];
#pragma unroll
            for (int h = 0; h < 2; h++) {
                const int row = r0g + h * 8;
                const size_t idx = (size_t)row * FDIM + g * 256 + cn;
                float2 pr = *(const float2*)(prior + idx);
                float2 zz;
                zz.x = (acc[nt][2 * h] * s0 + t0) * pr.x;
                zz.y = (acc[nt][2 * h + 1] * s1 + t1) * pr.y;
                *(float2*)(zout + idx) = zz;
            }
        }
    }
}

// ---------------- sparsemax: one warp per row, bisection + exact refinement ----------------
__global__ __launch_bounds__(256)
void k_sparsemax(const float* __restrict__ z, float* __restrict__ prior,
                 float* __restrict__ maskOut,
                 bf16* __restrict__ mfh, bf16* __restrict__ mfl)
{
    const int row = blockIdx.x * 8 + (threadIdx.x >> 5);
    const int lid = threadIdx.x & 31;
    const size_t base = (size_t)row * 512;
    float v[16];
#pragma unroll
    for (int q = 0; q < 4; q++) {
        float4 t = *(const float4*)(z + base + q * 128 + lid * 4);
        v[q * 4 + 0] = t.x; v[q * 4 + 1] = t.y; v[q * 4 + 2] = t.z; v[q * 4 + 3] = t.w;
    }
    float zmax = v[0];
#pragma unroll
    for (int i = 1; i < 16; i++) zmax = fmaxf(zmax, v[i]);
#pragma unroll
    for (int o = 16; o; o >>= 1) zmax = fmaxf(zmax, __shfl_xor_sync(0xffffffffu, zmax, o));

    float lo = zmax - 1.0f, hi = zmax;
    for (int it = 0; it < 28; it++) {
        float mid = 0.5f * (lo + hi);
        float s = 0.0f;
#pragma unroll
        for (int i = 0; i < 16; i++) s += fmaxf(v[i] - mid, 0.0f);
#pragma unroll
        for (int o = 16; o; o >>= 1) s += __shfl_xor_sync(0xffffffffu, s, o);
        if (s >= 1.0f) lo = mid; else hi = mid;
    }
    float sum = 0.0f, cnt = 0.0f;
#pragma unroll
    for (int i = 0; i < 16; i++) {
        if (v[i] > lo) { sum += v[i]; cnt += 1.0f; }
    }
#pragma unroll
    for (int o = 16; o; o >>= 1) {
        sum += __shfl_xor_sync(0xffffffffu, sum, o);
        cnt += __shfl_xor_sync(0xffffffffu, cnt, o);
    }
    const float tau = (sum - 1.0f) / cnt;

#pragma unroll
    for (int q = 0; q < 4; q++) {
        const size_t off = base + q * 128 + lid * 4;
        float4 mk;
        mk.x = fmaxf(v[q * 4 + 0] - tau, 0.0f);
        mk.y = fmaxf(v[q * 4 + 1] - tau, 0.0f);
        mk.z = fmaxf(v[q * 4 + 2] - tau, 0.0f);
        mk.w = fmaxf(v[q * 4 + 3] - tau, 0.0f);
        *(float4*)(maskOut + off) = mk;
        float4 pr = *(const float4*)(prior + off);
        pr.x *= (1.5f - mk.x); pr.y *= (1.5f - mk.y);
        pr.z *= (1.5f - mk.z); pr.w *= (1.5f - mk.w);
        *(float4*)(prior + off) = pr;
        float4 ft = *(const float4*)(g_feats + off);
        float m0 = mk.x * ft.x, m1 = mk.y * ft.y, m2 = mk.z * ft.z, m3 = mk.w * ft.w;
        bf16 h0 = __float2bfloat16(m0), h1 = __float2bfloat16(m1);
        bf16 h2 = __float2bfloat16(m2), h3 = __float2bfloat16(m3);
        __nv_bfloat162 p0; p0.x = h0; p0.y = h1;
        __nv_bfloat162 p1; p1.x = h2; p1.y = h3;
        *(__nv_bfloat162*)(mfh + off) = p0;
        *(__nv_bfloat162*)(mfh + off + 2) = p1;
        __nv_bfloat162 q0, q1;
        q0.x = __float2bfloat16(m0 - __bfloat162float(h0));
        q0.y = __float2bfloat16(m1 - __bfloat162float(h1));
        q1.x = __float2bfloat16(m2 - __bfloat162float(h2));
        q1.y = __float2bfloat16(m3 - __bfloat162float(h3));
        *(__nv_bfloat162*)(mfl + off) = q0;
        *(__nv_bfloat162*)(mfl + off + 2) = q1;
    }
}

// ---------------- final projection (SIMT; tiny) ----------------
__global__ __launch_bounds__(256)
void k_fin(const float* __restrict__ A, const float* __restrict__ W,
           const float* __restrict__ bias, float* __restrict__ C)
{
    __shared__ float As[16][128];
    __shared__ float Ws[16][64];
    const int tid = threadIdx.x;
    const int ty = tid >> 4, tx = tid & 15;
    const int row0 = blockIdx.y * 128;
    const int col0 = blockIdx.x * 64;

    float acc[8][4];
#pragma unroll
    for (int r = 0; r < 8; r++)
#pragma unroll
        for (int c = 0; c < 4; c++) acc[r][c] = 0.f;

    for (int kt = 0; kt < 128; kt += 16) {
#pragma unroll
        for (int l = 0; l < 2; l++) {
            int li = tid * 2 + l;
            int r = li >> 2, kq = (li & 3) * 4;
            float4 av = *(const float4*)(A + (size_t)(row0 + r) * 128 + kt + kq);
            As[kq + 0][r] = av.x; As[kq + 1][r] = av.y;
            As[kq + 2][r] = av.z; As[kq + 3][r] = av.w;
        }
        *(float4*)&Ws[tid >> 4][(tid & 15) * 4] =
            *(const float4*)(W + (size_t)(kt + (tid >> 4)) * 128 + col0 + (tid & 15) * 4);
        __syncthreads();
#pragma unroll
        for (int kk = 0; kk < 16; kk++) {
            float a[8];
            float4 a0 = *(float4*)&As[kk][ty * 8];
            float4 a1 = *(float4*)&As[kk][ty * 8 + 4];
            a[0] = a0.x; a[1] = a0.y; a[2] = a0.z; a[3] = a0.w;
            a[4] = a1.x; a[5] = a1.y; a[6] = a1.z; a[7] = a1.w;
            float4 w0 = *(float4*)&Ws[kk][tx * 4];
            float wv[4] = {w0.x, w0.y, w0.z, w0.w};
#pragma unroll
            for (int r = 0; r < 8; r++)
#pragma unroll
                for (int c = 0; c < 4; c++) acc[r][c] += a[r] * wv[c];
        }
        __syncthreads();
    }
#pragma unroll
    for (int r = 0; r < 8; r++) {
        int gr = row0 + ty * 8 + r;
#pragma unroll
        for (int c = 0; c < 4; c++) {
            int gc = col0 + tx * 4 + c;
            C[(size_t)gr * 128 + gc] = acc[r][c] + bias[gc];
        }
    }
}

// ---------------- launch ----------------
extern "C" void kernel_launch(void* const* d_in, const int* in_sizes, int n_in,
                              void* d_out, int out_size)
{
    const float* features = (const float*)d_in[0];
    const float* bn0_g = (const float*)d_in[1];
    const float* bn0_b = (const float*)d_in[2];
    const float* bn0_m = (const float*)d_in[3];
    const float* bn0_v = (const float*)d_in[4];
    const float* Ws0   = (const float*)d_in[5];
    const float* Ws1   = (const float*)d_in[6];
    const float* Wu    = (const float*)d_in[7];
    const float* ft_g  = (const float*)d_in[8];
    const float* ft_b  = (const float*)d_in[9];
    const float* ft_m  = (const float*)d_in[10];
    const float* ft_v  = (const float*)d_in[11];
    const float* W_att = (const float*)d_in[12];
    const float* att_g = (const float*)d_in[13];
    const float* att_b = (const float*)d_in[14];
    const float* att_m = (const float*)d_in[15];
    const float* att_v = (const float*)d_in[16];
    const float* Wf    = (const float*)d_in[17];
    const float* bf    = (const float*)d_in[18];

    float *feats, *zp, *prior, *acc;
    bf16 *Ah, *Al, *h0h, *h0l, *h1h, *h1l;
    bf16 *W0h, *W0l, *W1h, *W1l, *WUh, *WUl, *WAh, *WAl;
    float *fts, *ftt, *as, *at;
    cudaGetSymbolAddress((void**)&feats, g_feats);
    cudaGetSymbolAddress((void**)&Ah, g_Ah);
    cudaGetSymbolAddress((void**)&Al, g_Al);
    cudaGetSymbolAddress((void**)&h0h, g_h0h);
    cudaGetSymbolAddress((void**)&h0l, g_h0l);
    cudaGetSymbolAddress((void**)&h1h, g_h1h);
    cudaGetSymbolAddress((void**)&h1l, g_h1l);
    cudaGetSymbolAddress((void**)&zp, g_z);
    cudaGetSymbolAddress((void**)&prior, g_prior);
    cudaGetSymbolAddress((void**)&acc, g_acc);
    cudaGetSymbolAddress((void**)&W0h, g_W0h);
    cudaGetSymbolAddress((void**)&W0l, g_W0l);
    cudaGetSymbolAddress((void**)&W1h, g_W1h);
    cudaGetSymbolAddress((void**)&W1l, g_W1l);
    cudaGetSymbolAddress((void**)&WUh, g_WUh);
    cudaGetSymbolAddress((void**)&WUl, g_WUl);
    cudaGetSymbolAddress((void**)&WAh, g_WAh);
    cudaGetSymbolAddress((void**)&WAl, g_WAl);
    cudaGetSymbolAddress((void**)&fts, g_fts);
    cudaGetSymbolAddress((void**)&ftt, g_ftt);
    cudaGetSymbolAddress((void**)&as, g_as);
    cudaGetSymbolAddress((void**)&at, g_at);

    float* outF  = (float*)d_out;
    float* masks = outF + (size_t)BATCH * OUTD;

    static bool attr_set = false;
    if (!attr_set) {
        cudaFuncSetAttribute(k_mma<0>, cudaFuncAttributeMaxDynamicSharedMemorySize, SMEM_TOTAL);
        cudaFuncSetAttribute(k_mma<1>, cudaFuncAttributeMaxDynamicSharedMemorySize, SMEM_TOTAL);
        attr_set = true;
    }

    // ---- weight / bn prep ----
    k_prep_glu<<<(512 * 512 + 255) / 256, 256>>>(Ws0, 512, W0h, W0l);
    k_prep_glu<<<(512 * 256 + 255) / 256, 256>>>(Ws1, 256, W1h, W1l);
    for (int m = 0; m < 12; m++)
        k_prep_glu<<<(512 * 256 + 255) / 256, 256>>>(Wu + (size_t)m * 256 * 512, 256,
                                                     WUh + (size_t)m * 512 * 256,
                                                     WUl + (size_t)m * 512 * 256);
    k_prep_att<<<(5 * 512 * 128 + 255) / 256, 256>>>(W_att, WAh, WAl);
    k_prep_bn<<<(6 * 4 * 512 + 255) / 256, 256>>>(ft_g, ft_b, ft_m, ft_v,
                                                  att_g, att_b, att_m, att_v);
    k_init<<<(BATCH * FDIM) / 256, 256>>>(features, bn0_g, bn0_b, bn0_m, bn0_v);

    const dim3 gMma(2, BATCH / 128);

    auto ft_transformer = [&](int t, float* accOut) {
        const float* s0 = fts + (size_t)t * 4 * 512;
        const float* t0 = ftt + (size_t)t * 4 * 512;
        k_mma<0><<<gMma, 256, SMEM_TOTAL>>>(Ah, Al, 512, 512, W0h, W0l,
            s0, t0, nullptr, nullptr, h0h, h0l, nullptr, nullptr, nullptr);
        k_mma<0><<<gMma, 256, SMEM_TOTAL>>>(h0h, h0l, 256, 256, W1h, W1l,
            s0 + 512, t0 + 512, h0h, h0l, h1h, h1l, nullptr, nullptr, nullptr);
        k_mma<0><<<gMma, 256, SMEM_TOTAL>>>(h1h, h1l, 256, 256,
            WUh + (size_t)(t * 2 + 0) * 512 * 256, WUl + (size_t)(t * 2 + 0) * 512 * 256,
            s0 + 1024, t0 + 1024, h1h, h1l, h0h, h0l, nullptr, nullptr, nullptr);
        k_mma<0><<<gMma, 256, SMEM_TOTAL>>>(h0h, h0l, 256, 256,
            WUh + (size_t)(t * 2 + 1) * 512 * 256, WUl + (size_t)(t * 2 + 1) * 512 * 256,
            s0 + 1536, t0 + 1536, h0h, h0l, h1h, h1l, accOut, nullptr, nullptr);
    };

    ft_transformer(0, nullptr);

    for (int s = 0; s < STEPS; s++) {
        k_mma<1><<<gMma, 256, SMEM_TOTAL>>>(h1h + 128, h1l + 128, 256, 128,
            WAh + (size_t)s * 512 * 128, WAl + (size_t)s * 512 * 128,
            as + (size_t)s * 512, at + (size_t)s * 512,
            nullptr, nullptr, nullptr, nullptr, nullptr,
            prior, zp);
        k_sparsemax<<<BATCH / 8, 256>>>(zp, prior, masks + (size_t)s * BATCH * FDIM, Ah, Al);
        ft_transformer(s + 1, acc);
    }

    k_fin<<<dim3(2, BATCH / 128), 256>>>(acc, Wf, bf, outF);
}

// round 4
// speedup vs baseline: 2.3645x; 1.1724x over previous
#include <cuda_runtime.h>
#include <cuda_bf16.h>
#include <math.h>
#include <stdint.h>

#define BATCH 32768
#define FDIM 512
#define HS 256
#define UU 512
#define OUTD 128
#define STEPS 5
#define EPSBN 1e-5f

typedef __nv_bfloat16 bf16;

// ---------------- scratch (device globals; no allocation) ----------------
__device__ float g_feats[BATCH * FDIM];
__device__ bf16  g_Ah[BATCH * FDIM];
__device__ bf16  g_Al[BATCH * FDIM];
__device__ bf16  g_h0h[BATCH * HS], g_h0l[BATCH * HS];
__device__ bf16  g_h1h[BATCH * HS], g_h1l[BATCH * HS];
__device__ float g_z[BATCH * FDIM];
__device__ float g_prior[BATCH * FDIM];
__device__ float g_acc[BATCH * OUTD];

// prepped weights ([N,K] bf16 hi/lo; GLU ones N-permuted with 8-col a/b interleave)
__device__ bf16 g_W0h[512 * 512], g_W0l[512 * 512];
__device__ bf16 g_W1h[512 * 256], g_W1l[512 * 256];
__device__ bf16 g_WUh[12 * 512 * 256], g_WUl[12 * 512 * 256];
__device__ bf16 g_WAh[5 * 512 * 128], g_WAl[5 * 512 * 128];
__device__ float g_fts[6 * 4 * 512], g_ftt[6 * 4 * 512];
__device__ float g_as[5 * 512], g_at[5 * 512];

// ---------------- PTX helpers ----------------
__device__ __forceinline__ uint32_t smem_u32(const void* p) {
    uint32_t a;
    asm("{ .reg .u64 t; cvta.to.shared.u64 t, %1; cvt.u32.u64 %0, t; }" : "=r"(a) : "l"(p));
    return a;
}
__device__ __forceinline__ void cpa16(uint32_t s, const void* g) {
    asm volatile("cp.async.cg.shared.global [%0], [%1], 16;" :: "r"(s), "l"(g));
}
__device__ __forceinline__ void cpa_commit() {
    asm volatile("cp.async.commit_group;" ::: "memory");
}
template<int N>
__device__ __forceinline__ void cpa_wait() {
    asm volatile("cp.async.wait_group %0;" :: "n"(N) : "memory");
}
__device__ __forceinline__ void ldm4(uint32_t* v, uint32_t addr) {
    asm volatile("ldmatrix.sync.aligned.m8n8.x4.shared.b16 {%0,%1,%2,%3}, [%4];"
                 : "=r"(v[0]), "=r"(v[1]), "=r"(v[2]), "=r"(v[3]) : "r"(addr));
}
__device__ __forceinline__ void mma16(float* c, const uint32_t* a, uint32_t b0, uint32_t b1) {
    asm volatile("mma.sync.aligned.m16n8k16.row.col.f32.bf16.bf16.f32 "
                 "{%0,%1,%2,%3}, {%4,%5,%6,%7}, {%8,%9}, {%0,%1,%2,%3};"
                 : "+f"(c[0]), "+f"(c[1]), "+f"(c[2]), "+f"(c[3])
                 : "r"(a[0]), "r"(a[1]), "r"(a[2]), "r"(a[3]), "r"(b0), "r"(b1));
}

// ---------------- prep: all GLU weights in one kernel ----------------
// prepped row n: q=n>>4, rr=n&15, half=rr>>3, jl=rr&7 -> orig col = half*256 + q*8 + jl
__device__ __forceinline__ void prep_one(const float* W, int K, int idx,
                                         bf16* oh, bf16* ol)
{
    int n = idx / K, k = idx - n * K;
    int q = n >> 4, rr = n & 15, half = rr >> 3, jl = rr & 7;
    int col = (half ? 256 : 0) + q * 8 + jl;
    float v = W[(size_t)k * 512 + col];
    bf16 h = __float2bfloat16(v);
    oh[idx] = h;
    ol[idx] = __float2bfloat16(v - __bfloat162float(h));
}

__global__ void k_prep_glu_all(const float* __restrict__ Ws0,
                               const float* __restrict__ Ws1,
                               const float* __restrict__ Wu)
{
    int idx = blockIdx.x * 256 + threadIdx.x;
    const int N0 = 512 * 512;            // Ws0
    const int N1 = N0 + 512 * 256;       // Ws1
    const int N2 = N1 + 12 * 512 * 256;  // Wu
    if (idx < N0) {
        prep_one(Ws0, 512, idx, g_W0h, g_W0l);
    } else if (idx < N1) {
        prep_one(Ws1, 256, idx - N0, g_W1h, g_W1l);
    } else if (idx < N2) {
        int r = idx - N1;
        int mi = r / (512 * 256);
        int li = r - mi * (512 * 256);
        prep_one(Wu + (size_t)mi * 256 * 512, 256, li,
                 g_WUh + (size_t)mi * 512 * 256, g_WUl + (size_t)mi * 512 * 256);
    }
}

__global__ void k_prep_att_bn(const float* __restrict__ Wa,
                              const float* __restrict__ fg, const float* __restrict__ fb,
                              const float* __restrict__ fm, const float* __restrict__ fv,
                              const float* __restrict__ ag, const float* __restrict__ ab,
                              const float* __restrict__ am, const float* __restrict__ av)
{
    int idx = blockIdx.x * 256 + threadIdx.x;
    if (idx < 5 * 512 * 128) {
        int s = idx / (512 * 128);
        int r = idx - s * 512 * 128;
        int n = r >> 7, k = r & 127;
        float v = Wa[(size_t)s * 128 * 512 + (size_t)k * 512 + n];
        bf16 h = __float2bfloat16(v);
        g_WAh[idx] = h;
        g_WAl[idx] = __float2bfloat16(v - __bfloat162float(h));
    }
    if (idx < 6 * 4 * 512) {
        float s = fg[idx] * rsqrtf(fv[idx] + EPSBN);
        g_fts[idx] = s;
        g_ftt[idx] = fb[idx] - fm[idx] * s;
    }
    if (idx < 5 * 512) {
        float s = ag[idx] * rsqrtf(av[idx] + EPSBN);
        g_as[idx] = s;
        g_at[idx] = ab[idx] - am[idx] * s;
    }
}

__global__ void k_init(const float* __restrict__ feat,
                       const float* __restrict__ g, const float* __restrict__ b,
                       const float* __restrict__ m, const float* __restrict__ v)
{
    int i = blockIdx.x * blockDim.x + threadIdx.x;
    if (i < BATCH * FDIM) {
        int c = i & (FDIM - 1);
        float f = g[c] * (feat[i] - m[c]) * rsqrtf(v[c] + EPSBN) + b[c];
        g_feats[i] = f;
        bf16 h = __float2bfloat16(f);
        g_Ah[i] = h;
        g_Al[i] = __float2bfloat16(f - __bfloat162float(h));
        g_prior[i] = 1.0f;
        if (i < BATCH * OUTD) g_acc[i] = 0.0f;
    }
}

// ---------------- HMMA GEMM: MODE 0 = GLU, MODE 1 = attention ----------------
// 512 threads, warp grid 4(M)x4(N), warp tile 32x64. BM=128, BN=256, BK=64.
#define STAGE_BYTES 98304     // Ah 16K | Al 16K | Bh 32K | Bl 32K
#define PARAM_OFF   (2 * STAGE_BYTES)
#define SMEM_TOTAL  (PARAM_OFF + 2048)

template<int MODE>
__global__ __launch_bounds__(512)
void k_mma(const bf16* __restrict__ Ah, const bf16* __restrict__ Al, int lda, int K,
           const bf16* __restrict__ Bh, const bf16* __restrict__ Bl,
           const float* __restrict__ bs, const float* __restrict__ bt,
           const bf16* __restrict__ resh, const bf16* __restrict__ resl,
           bf16* __restrict__ outh, bf16* __restrict__ outl,
           float* __restrict__ accp,
           const float* __restrict__ prior, float* __restrict__ zout)
{
    extern __shared__ __align__(128) char smem[];
    const int tid = threadIdx.x, wid = tid >> 5, lid = tid & 31;
    const int wm = wid >> 2, wn = wid & 3;
    const int g = blockIdx.x;
    const int row0 = blockIdx.y * 128;
    const uint32_t sb = smem_u32(smem);

    // stage fused-BN params (prepped-N order)
    if (tid < 256) {
        float* sE = (float*)(smem + PARAM_OFF);
        float* tE = (float*)(smem + PARAM_OFF + 1024);
        int col;
        if (MODE == 0) {
            int q2 = tid >> 4, rr = tid & 15, half = rr >> 3, jl = rr & 7;
            col = (half ? 256 : 0) + g * 128 + q2 * 8 + jl;
        } else {
            col = g * 256 + tid;
        }
        sE[tid] = bs[col];
        tE[tid] = bt[col];
    }

    float acc[16][4];
#pragma unroll
    for (int i = 0; i < 16; i++)
#pragma unroll
        for (int j = 0; j < 4; j++) acc[i][j] = 0.0f;

    const int nch = K >> 6;

    auto load_stage = [&](int ch) {
        const int s = ch & 1, kt = ch << 6;
        const uint32_t st = sb + s * STAGE_BYTES;
#pragma unroll
        for (int i = 0; i < 2; i++) {
            int idx = tid + i * 512;
            int r = idx >> 3, c = idx & 7;
            uint32_t so = (uint32_t)(r * 128 + ((c ^ (r & 7)) << 4));
            cpa16(st + so,         Ah + (size_t)(row0 + r) * lda + kt + c * 8);
            cpa16(st + 16384 + so, Al + (size_t)(row0 + r) * lda + kt + c * 8);
        }
#pragma unroll
        for (int i = 0; i < 4; i++) {
            int idx = tid + i * 512;
            int r = idx >> 3, c = idx & 7;
            uint32_t so = (uint32_t)(r * 128 + ((c ^ (r & 7)) << 4));
            cpa16(st + 32768 + so, Bh + (size_t)(g * 256 + r) * K + kt + c * 8);
            cpa16(st + 65536 + so, Bl + (size_t)(g * 256 + r) * K + kt + c * 8);
        }
    };

    load_stage(0);
    cpa_commit();

    const int lr = lid & 15, lc = lid >> 4;

    for (int ch = 0; ch < nch; ch++) {
        if (ch + 1 < nch) { load_stage(ch + 1); cpa_commit(); cpa_wait<1>(); }
        else              { cpa_wait<0>(); }
        __syncthreads();
        const uint32_t st = sb + (ch & 1) * STAGE_BYTES;
#pragma unroll
        for (int ks = 0; ks < 4; ks++) {
            uint32_t ah[2][4], al[2][4];
#pragma unroll
            for (int m = 0; m < 2; m++) {
                int r = wm * 32 + m * 16 + lr;
                int cc = 2 * ks + lc;
                uint32_t ad = st + r * 128 + ((cc ^ (r & 7)) << 4);
                ldm4(ah[m], ad);
                ldm4(al[m], ad + 16384);
            }
#pragma unroll
            for (int nb = 0; nb < 4; nb++) {
                int r = wn * 64 + nb * 16 + lr;
                int cc = 2 * ks + lc;
                uint32_t bd = st + 32768 + r * 128 + ((cc ^ (r & 7)) << 4);
                uint32_t bh[4], bl[4];
                ldm4(bh, bd);
                ldm4(bl, bd + 32768);
#pragma unroll
                for (int m = 0; m < 2; m++) {
                    mma16(acc[m * 8 + 2 * nb],     ah[m], bh[0], bh[2]);
                    mma16(acc[m * 8 + 2 * nb + 1], ah[m], bh[1], bh[3]);
                    mma16(acc[m * 8 + 2 * nb],     ah[m], bl[0], bl[2]);
                    mma16(acc[m * 8 + 2 * nb + 1], ah[m], bl[1], bl[3]);
                    mma16(acc[m * 8 + 2 * nb],     al[m], bh[0], bh[2]);
                    mma16(acc[m * 8 + 2 * nb + 1], al[m], bh[1], bh[3]);
                }
            }
        }
        __syncthreads();
    }

    // ---------------- epilogue ----------------
    const float* sE = (const float*)(smem + PARAM_OFF);
    const float* tE = (const float*)(smem + PARAM_OFF + 1024);
    const int gid = lid >> 2, tp = lid & 3;

    if (MODE == 0) {
#pragma unroll
        for (int m = 0; m < 2; m++) {
#pragma unroll
            for (int t = 0; t < 4; t++) {
                const int ja = wn * 64 + t * 16 + tp * 2;     // prepped local idx (a)
                const int jb = ja + 8;                        // (b)
                const int cn = g * 128 + (wn * 4 + t) * 8 + tp * 2;  // output col
                const float sa0 = sE[ja], sa1 = sE[ja + 1];
                const float ta0 = tE[ja], ta1 = tE[ja + 1];
                const float sb0 = sE[jb], sb1 = sE[jb + 1];
                const float tb0 = tE[jb], tb1 = tE[jb + 1];
                const float* ca = acc[m * 8 + 2 * t];
                const float* cb = acc[m * 8 + 2 * t + 1];
#pragma unroll
                for (int h = 0; h < 2; h++) {
                    const int row = row0 + wm * 32 + m * 16 + gid + h * 8;
                    float xa0 = ca[2 * h] * sa0 + ta0;
                    float xa1 = ca[2 * h + 1] * sa1 + ta1;
                    float xb0 = cb[2 * h] * sb0 + tb0;
                    float xb1 = cb[2 * h + 1] * sb1 + tb1;
                    float o0 = xa0 * (1.0f / (1.0f + __expf(-xb0)));
                    float o1 = xa1 * (1.0f / (1.0f + __expf(-xb1)));
                    const size_t ob = (size_t)row * HS + cn;
                    if (resh) {
                        __nv_bfloat162 rh = *(const __nv_bfloat162*)(resh + ob);
                        __nv_bfloat162 rl = *(const __nv_bfloat162*)(resl + ob);
                        o0 = fmaf(__bfloat162float(rh.x) + __bfloat162float(rl.x),
                                  0.70710678118654752f, o0);
                        o1 = fmaf(__bfloat162float(rh.y) + __bfloat162float(rl.y),
                                  0.70710678118654752f, o1);
                    }
                    bf16 h0 = __float2bfloat16(o0);
                    bf16 h1 = __float2bfloat16(o1);
                    __nv_bfloat162 hh; hh.x = h0; hh.y = h1;
                    *(__nv_bfloat162*)(outh + ob) = hh;
                    __nv_bfloat162 ll;
                    ll.x = __float2bfloat16(o0 - __bfloat162float(h0));
                    ll.y = __float2bfloat16(o1 - __bfloat162float(h1));
                    *(__nv_bfloat162*)(outl + ob) = ll;
                    if (accp && g == 0) {
                        float2* ap = (float2*)(accp + (size_t)row * OUTD + cn);
                        float2 av = *ap;
                        av.x += fmaxf(o0, 0.0f);
                        av.y += fmaxf(o1, 0.0f);
                        *ap = av;
                    }
                }
            }
        }
    } else {
#pragma unroll
        for (int m = 0; m < 2; m++) {
#pragma unroll
            for (int nb2 = 0; nb2 < 8; nb2++) {
                const int cn = wn * 64 + nb2 * 8 + tp * 2;
                const float s0 = sE[cn], s1 = sE[cn + 1];
                const float t0 = tE[cn], t1 = tE[cn + 1];
                const float* ca = acc[m * 8 + nb2];
#pragma unroll
                for (int h = 0; h < 2; h++) {
                    const int row = row0 + wm * 32 + m * 16 + gid + h * 8;
                    const size_t idx = (size_t)row * FDIM + g * 256 + cn;
                    float2 pr = *(const float2*)(prior + idx);
                    float2 zz;
                    zz.x = (ca[2 * h] * s0 + t0) * pr.x;
                    zz.y = (ca[2 * h + 1] * s1 + t1) * pr.y;
                    *(float2*)(zout + idx) = zz;
                }
            }
        }
    }
}

// ---------------- sparsemax: one warp per row ----------------
__global__ __launch_bounds__(256)
void k_sparsemax(const float* __restrict__ z, float* __restrict__ prior,
                 float* __restrict__ maskOut,
                 bf16* __restrict__ mfh, bf16* __restrict__ mfl)
{
    const int row = blockIdx.x * 8 + (threadIdx.x >> 5);
    const int lid = threadIdx.x & 31;
    const size_t base = (size_t)row * 512;
    float v[16];
#pragma unroll
    for (int q = 0; q < 4; q++) {
        float4 t = *(const float4*)(z + base + q * 128 + lid * 4);
        v[q * 4 + 0] = t.x; v[q * 4 + 1] = t.y; v[q * 4 + 2] = t.z; v[q * 4 + 3] = t.w;
    }
    float zmax = v[0];
#pragma unroll
    for (int i = 1; i < 16; i++) zmax = fmaxf(zmax, v[i]);
#pragma unroll
    for (int o = 16; o; o >>= 1) zmax = fmaxf(zmax, __shfl_xor_sync(0xffffffffu, zmax, o));

    float lo = zmax - 1.0f, hi = zmax;
    for (int it = 0; it < 28; it++) {
        float mid = 0.5f * (lo + hi);
        float s = 0.0f;
#pragma unroll
        for (int i = 0; i < 16; i++) s += fmaxf(v[i] - mid, 0.0f);
#pragma unroll
        for (int o = 16; o; o >>= 1) s += __shfl_xor_sync(0xffffffffu, s, o);
        if (s >= 1.0f) lo = mid; else hi = mid;
    }
    float sum = 0.0f, cnt = 0.0f;
#pragma unroll
    for (int i = 0; i < 16; i++) {
        if (v[i] > lo) { sum += v[i]; cnt += 1.0f; }
    }
#pragma unroll
    for (int o = 16; o; o >>= 1) {
        sum += __shfl_xor_sync(0xffffffffu, sum, o);
        cnt += __shfl_xor_sync(0xffffffffu, cnt, o);
    }
    const float tau = (sum - 1.0f) / cnt;

#pragma unroll
    for (int q = 0; q < 4; q++) {
        const size_t off = base + q * 128 + lid * 4;
        float4 mk;
        mk.x = fmaxf(v[q * 4 + 0] - tau, 0.0f);
        mk.y = fmaxf(v[q * 4 + 1] - tau, 0.0f);
        mk.z = fmaxf(v[q * 4 + 2] - tau, 0.0f);
        mk.w = fmaxf(v[q * 4 + 3] - tau, 0.0f);
        *(float4*)(maskOut + off) = mk;
        float4 pr = *(const float4*)(prior + off);
        pr.x *= (1.5f - mk.x); pr.y *= (1.5f - mk.y);
        pr.z *= (1.5f - mk.z); pr.w *= (1.5f - mk.w);
        *(float4*)(prior + off) = pr;
        float4 ft = *(const float4*)(g_feats + off);
        float m0 = mk.x * ft.x, m1 = mk.y * ft.y, m2 = mk.z * ft.z, m3 = mk.w * ft.w;
        bf16 h0 = __float2bfloat16(m0), h1 = __float2bfloat16(m1);
        bf16 h2 = __float2bfloat16(m2), h3 = __float2bfloat16(m3);
        __nv_bfloat162 p0; p0.x = h0; p0.y = h1;
        __nv_bfloat162 p1; p1.x = h2; p1.y = h3;
        *(__nv_bfloat162*)(mfh + off) = p0;
        *(__nv_bfloat162*)(mfh + off + 2) = p1;
        __nv_bfloat162 q0, q1;
        q0.x = __float2bfloat16(m0 - __bfloat162float(h0));
        q0.y = __float2bfloat16(m1 - __bfloat162float(h1));
        q1.x = __float2bfloat16(m2 - __bfloat162float(h2));
        q1.y = __float2bfloat16(m3 - __bfloat162float(h3));
        *(__nv_bfloat162*)(mfl + off) = q0;
        *(__nv_bfloat162*)(mfl + off + 2) = q1;
    }
}

// ---------------- final projection ----------------
__global__ __launch_bounds__(256)
void k_fin(const float* __restrict__ A, const float* __restrict__ W,
           const float* __restrict__ bias, float* __restrict__ C)
{
    __shared__ float As[16][128];
    __shared__ float Ws[16][64];
    const int tid = threadIdx.x;
    const int ty = tid >> 4, tx = tid & 15;
    const int row0 = blockIdx.y * 128;
    const int col0 = blockIdx.x * 64;

    float acc[8][4];
#pragma unroll
    for (int r = 0; r < 8; r++)
#pragma unroll
        for (int c = 0; c < 4; c++) acc[r][c] = 0.f;

    for (int kt = 0; kt < 128; kt += 16) {
#pragma unroll
        for (int l = 0; l < 2; l++) {
            int li = tid * 2 + l;
            int r = li >> 2, kq = (li & 3) * 4;
            float4 av = *(const float4*)(A + (size_t)(row0 + r) * 128 + kt + kq);
            As[kq + 0][r] = av.x; As[kq + 1][r] = av.y;
            As[kq + 2][r] = av.z; As[kq + 3][r] = av.w;
        }
        *(float4*)&Ws[tid >> 4][(tid & 15) * 4] =
            *(const float4*)(W + (size_t)(kt + (tid >> 4)) * 128 + col0 + (tid & 15) * 4);
        __syncthreads();
#pragma unroll
        for (int kk = 0; kk < 16; kk++) {
            float a[8];
            float4 a0 = *(float4*)&As[kk][ty * 8];
            float4 a1 = *(float4*)&As[kk][ty * 8 + 4];
            a[0] = a0.x; a[1] = a0.y; a[2] = a0.z; a[3] = a0.w;
            a[4] = a1.x; a[5] = a1.y; a[6] = a1.z; a[7] = a1.w;
            float4 w0 = *(float4*)&Ws[kk][tx * 4];
            float wv[4] = {w0.x, w0.y, w0.z, w0.w};
#pragma unroll
            for (int r = 0; r < 8; r++)
#pragma unroll
                for (int c = 0; c < 4; c++) acc[r][c] += a[r] * wv[c];
        }
        __syncthreads();
    }
#pragma unroll
    for (int r = 0; r < 8; r++) {
        int gr = row0 + ty * 8 + r;
#pragma unroll
        for (int c = 0; c < 4; c++) {
            int gc = col0 + tx * 4 + c;
            C[(size_t)gr * 128 + gc] = acc[r][c] + bias[gc];
        }
    }
}

// ---------------- launch ----------------
extern "C" void kernel_launch(void* const* d_in, const int* in_sizes, int n_in,
                              void* d_out, int out_size)
{
    const float* features = (const float*)d_in[0];
    const float* bn0_g = (const float*)d_in[1];
    const float* bn0_b = (const float*)d_in[2];
    const float* bn0_m = (const float*)d_in[3];
    const float* bn0_v = (const float*)d_in[4];
    const float* Ws0   = (const float*)d_in[5];
    const float* Ws1   = (const float*)d_in[6];
    const float* Wu    = (const float*)d_in[7];
    const float* ft_g  = (const float*)d_in[8];
    const float* ft_b  = (const float*)d_in[9];
    const float* ft_m  = (const float*)d_in[10];
    const float* ft_v  = (const float*)d_in[11];
    const float* W_att = (const float*)d_in[12];
    const float* att_g = (const float*)d_in[13];
    const float* att_b = (const float*)d_in[14];
    const float* att_m = (const float*)d_in[15];
    const float* att_v = (const float*)d_in[16];
    const float* Wf    = (const float*)d_in[17];
    const float* bf    = (const float*)d_in[18];

    float *zp, *prior, *acc;
    bf16 *Ah, *Al, *h0h, *h0l, *h1h, *h1l;
    bf16 *W0h, *W0l, *W1h, *W1l, *WUh, *WUl, *WAh, *WAl;
    float *fts, *ftt, *as, *at;
    cudaGetSymbolAddress((void**)&Ah, g_Ah);
    cudaGetSymbolAddress((void**)&Al, g_Al);
    cudaGetSymbolAddress((void**)&h0h, g_h0h);
    cudaGetSymbolAddress((void**)&h0l, g_h0l);
    cudaGetSymbolAddress((void**)&h1h, g_h1h);
    cudaGetSymbolAddress((void**)&h1l, g_h1l);
    cudaGetSymbolAddress((void**)&zp, g_z);
    cudaGetSymbolAddress((void**)&prior, g_prior);
    cudaGetSymbolAddress((void**)&acc, g_acc);
    cudaGetSymbolAddress((void**)&W0h, g_W0h);
    cudaGetSymbolAddress((void**)&W0l, g_W0l);
    cudaGetSymbolAddress((void**)&W1h, g_W1h);
    cudaGetSymbolAddress((void**)&W1l, g_W1l);
    cudaGetSymbolAddress((void**)&WUh, g_WUh);
    cudaGetSymbolAddress((void**)&WUl, g_WUl);
    cudaGetSymbolAddress((void**)&WAh, g_WAh);
    cudaGetSymbolAddress((void**)&WAl, g_WAl);
    cudaGetSymbolAddress((void**)&fts, g_fts);
    cudaGetSymbolAddress((void**)&ftt, g_ftt);
    cudaGetSymbolAddress((void**)&as, g_as);
    cudaGetSymbolAddress((void**)&at, g_at);

    float* outF  = (float*)d_out;
    float* masks = outF + (size_t)BATCH * OUTD;

    static bool attr_set = false;
    if (!attr_set) {
        cudaFuncSetAttribute(k_mma<0>, cudaFuncAttributeMaxDynamicSharedMemorySize, SMEM_TOTAL);
        cudaFuncSetAttribute(k_mma<1>, cudaFuncAttributeMaxDynamicSharedMemorySize, SMEM_TOTAL);
        attr_set = true;
    }

    // ---- prep (2 launches) + init ----
    const int PREP_N = 512 * 512 + 512 * 256 + 12 * 512 * 256;
    k_prep_glu_all<<<(PREP_N + 255) / 256, 256>>>(Ws0, Ws1, Wu);
    k_prep_att_bn<<<(5 * 512 * 128 + 255) / 256, 256>>>(W_att, ft_g, ft_b, ft_m, ft_v,
                                                        att_g, att_b, att_m, att_v);
    k_init<<<(BATCH * FDIM) / 256, 256>>>(features, bn0_g, bn0_b, bn0_m, bn0_v);

    const dim3 gMma(2, BATCH / 128);

    auto ft_transformer = [&](int t, float* accOut) {
        const float* s0 = fts + (size_t)t * 4 * 512;
        const float* t0 = ftt + (size_t)t * 4 * 512;
        k_mma<0><<<gMma, 512, SMEM_TOTAL>>>(Ah, Al, 512, 512, W0h, W0l,
            s0, t0, nullptr, nullptr, h0h, h0l, nullptr, nullptr, nullptr);
        k_mma<0><<<gMma, 512, SMEM_TOTAL>>>(h0h, h0l, 256, 256, W1h, W1l,
            s0 + 512, t0 + 512, h0h, h0l, h1h, h1l, nullptr, nullptr, nullptr);
        k_mma<0><<<gMma, 512, SMEM_TOTAL>>>(h1h, h1l, 256, 256,
            WUh + (size_t)(t * 2 + 0) * 512 * 256, WUl + (size_t)(t * 2 + 0) * 512 * 256,
            s0 + 1024, t0 + 1024, h1h, h1l, h0h, h0l, nullptr, nullptr, nullptr);
        k_mma<0><<<gMma, 512, SMEM_TOTAL>>>(h0h, h0l, 256, 256,
            WUh + (size_t)(t * 2 + 1) * 512 * 256, WUl + (size_t)(t * 2 + 1) * 512 * 256,
            s0 + 1536, t0 + 1536, h0h, h0l, h1h, h1l, accOut, nullptr, nullptr);
    };

    ft_transformer(0, nullptr);

    for (int s = 0; s < STEPS; s++) {
        k_mma<1><<<gMma, 512, SMEM_TOTAL>>>(h1h + 128, h1l + 128, 256, 128,
            WAh + (size_t)s * 512 * 128, WAl + (size_t)s * 512 * 128,
            as + (size_t)s * 512, at + (size_t)s * 512,
            nullptr, nullptr, nullptr, nullptr, nullptr,
            prior, zp);
        k_sparsemax<<<BATCH / 8, 256>>>(zp, prior, masks + (size_t)s * BATCH * FDIM, Ah, Al);
        ft_transformer(s + 1, acc);
    }

    k_fin<<<dim3(2, BATCH / 128), 256>>>(acc, Wf, bf, outF);
}

// round 5
// speedup vs baseline: 3.0253x; 1.2794x over previous
#include <cuda_runtime.h>
#include <cuda_fp16.h>
#include <math.h>
#include <stdint.h>

#define BATCH 32768
#define FDIM 512
#define HS 256
#define OUTD 128
#define STEPS 5
#define EPSBN 1e-5f

typedef __half fp16;

// ---------------- scratch (device globals; no allocation) ----------------
__device__ float g_feats[BATCH * FDIM];
__device__ fp16  g_Ah[BATCH * FDIM];
__device__ fp16  g_Al[BATCH * FDIM];
__device__ fp16  g_h0h[BATCH * HS], g_h0l[BATCH * HS];
__device__ fp16  g_h1h[BATCH * HS], g_h1l[BATCH * HS];
__device__ float g_z[BATCH * FDIM];
__device__ float g_prior[BATCH * FDIM];
__device__ float g_acc[BATCH * OUTD];

// prepped weights ([N,K] fp16 single; GLU ones N-permuted with 8-col a/b interleave)
__device__ fp16 g_W0[512 * 512];
__device__ fp16 g_W1[512 * 256];
__device__ fp16 g_WU[12 * 512 * 256];
__device__ fp16 g_WA[5 * 512 * 128];
__device__ float g_fts[6 * 4 * 512], g_ftt[6 * 4 * 512];
__device__ float g_as[5 * 512], g_at[5 * 512];

// ---------------- PTX helpers ----------------
__device__ __forceinline__ uint32_t smem_u32(const void* p) {
    uint32_t a;
    asm("{ .reg .u64 t; cvta.to.shared.u64 t, %1; cvt.u32.u64 %0, t; }" : "=r"(a) : "l"(p));
    return a;
}
__device__ __forceinline__ void cpa16(uint32_t s, const void* g) {
    asm volatile("cp.async.cg.shared.global [%0], [%1], 16;" :: "r"(s), "l"(g));
}
__device__ __forceinline__ void cpa_commit() {
    asm volatile("cp.async.commit_group;" ::: "memory");
}
template<int N>
__device__ __forceinline__ void cpa_wait() {
    asm volatile("cp.async.wait_group %0;" :: "n"(N) : "memory");
}
__device__ __forceinline__ void ldm4(uint32_t* v, uint32_t addr) {
    asm volatile("ldmatrix.sync.aligned.m8n8.x4.shared.b16 {%0,%1,%2,%3}, [%4];"
                 : "=r"(v[0]), "=r"(v[1]), "=r"(v[2]), "=r"(v[3]) : "r"(addr));
}
__device__ __forceinline__ void mma16(float* c, const uint32_t* a, uint32_t b0, uint32_t b1) {
    asm volatile("mma.sync.aligned.m16n8k16.row.col.f32.f16.f16.f32 "
                 "{%0,%1,%2,%3}, {%4,%5,%6,%7}, {%8,%9}, {%0,%1,%2,%3};"
                 : "+f"(c[0]), "+f"(c[1]), "+f"(c[2]), "+f"(c[3])
                 : "r"(a[0]), "r"(a[1]), "r"(a[2]), "r"(a[3]), "r"(b0), "r"(b1));
}

// ---------------- prep ----------------
// prepped row n: q=n>>4, rr=n&15, half=rr>>3, jl=rr&7 -> orig col = half*256 + q*8 + jl
__device__ __forceinline__ void prep_one(const float* W, int K, int idx, fp16* o)
{
    int n = idx / K, k = idx - n * K;
    int q = n >> 4, rr = n & 15, half = rr >> 3, jl = rr & 7;
    int col = (half ? 256 : 0) + q * 8 + jl;
    o[idx] = __float2half_rn(W[(size_t)k * 512 + col]);
}

__global__ void k_prep_glu_all(const float* __restrict__ Ws0,
                               const float* __restrict__ Ws1,
                               const float* __restrict__ Wu)
{
    int idx = blockIdx.x * 256 + threadIdx.x;
    const int N0 = 512 * 512;
    const int N1 = N0 + 512 * 256;
    const int N2 = N1 + 12 * 512 * 256;
    if (idx < N0) {
        prep_one(Ws0, 512, idx, g_W0);
    } else if (idx < N1) {
        prep_one(Ws1, 256, idx - N0, g_W1);
    } else if (idx < N2) {
        int r = idx - N1;
        int mi = r / (512 * 256);
        int li = r - mi * (512 * 256);
        prep_one(Wu + (size_t)mi * 256 * 512, 256, li, g_WU + (size_t)mi * 512 * 256);
    }
}

__global__ void k_prep_att_bn(const float* __restrict__ Wa,
                              const float* __restrict__ fg, const float* __restrict__ fb,
                              const float* __restrict__ fm, const float* __restrict__ fv,
                              const float* __restrict__ ag, const float* __restrict__ ab,
                              const float* __restrict__ am, const float* __restrict__ av)
{
    int idx = blockIdx.x * 256 + threadIdx.x;
    if (idx < 5 * 512 * 128) {
        int s = idx / (512 * 128);
        int r = idx - s * 512 * 128;
        int n = r >> 7, k = r & 127;
        g_WA[idx] = __float2half_rn(Wa[(size_t)s * 128 * 512 + (size_t)k * 512 + n]);
    }
    if (idx < 6 * 4 * 512) {
        float s = fg[idx] * rsqrtf(fv[idx] + EPSBN);
        g_fts[idx] = s;
        g_ftt[idx] = fb[idx] - fm[idx] * s;
    }
    if (idx < 5 * 512) {
        float s = ag[idx] * rsqrtf(av[idx] + EPSBN);
        g_as[idx] = s;
        g_at[idx] = ab[idx] - am[idx] * s;
    }
}

__global__ void k_init(const float* __restrict__ feat,
                       const float* __restrict__ g, const float* __restrict__ b,
                       const float* __restrict__ m, const float* __restrict__ v)
{
    int i = blockIdx.x * blockDim.x + threadIdx.x;
    if (i < BATCH * FDIM) {
        int c = i & (FDIM - 1);
        float f = g[c] * (feat[i] - m[c]) * rsqrtf(v[c] + EPSBN) + b[c];
        g_feats[i] = f;
        fp16 h = __float2half_rn(f);
        g_Ah[i] = h;
        g_Al[i] = __float2half_rn(f - __half2float(h));
        g_prior[i] = 1.0f;
        if (i < BATCH * OUTD) g_acc[i] = 0.0f;
    }
}

// ---------------- HMMA GEMM: MODE 0 = GLU, MODE 1 = attention ----------------
// 512 threads, warp grid 4(M)x4(N), warp tile 32x64. BM=128, BN=256, BK=64.
// D = (Ah + Al) * W^T, fp32 accum; W single fp16.
#define STAGE_BYTES 65536     // Ah 16K | Al 16K | B 32K
#define PARAM_OFF   (3 * STAGE_BYTES)
#define SMEM_TOTAL  (PARAM_OFF + 2048)

template<int MODE>
__global__ __launch_bounds__(512)
void k_mma(const fp16* __restrict__ Ah, const fp16* __restrict__ Al, int lda, int K,
           const fp16* __restrict__ B,
           const float* __restrict__ bs, const float* __restrict__ bt,
           const fp16* __restrict__ resh, const fp16* __restrict__ resl,
           fp16* __restrict__ outh, fp16* __restrict__ outl,
           float* __restrict__ accp,
           const float* __restrict__ prior, float* __restrict__ zout)
{
    extern __shared__ __align__(128) char smem[];
    const int tid = threadIdx.x, wid = tid >> 5, lid = tid & 31;
    const int wm = wid >> 2, wn = wid & 3;
    const int g = blockIdx.x;
    const int row0 = blockIdx.y * 128;
    const uint32_t sb = smem_u32(smem);

    // stage fused-BN params
    if (tid < 256) {
        float* sE = (float*)(smem + PARAM_OFF);
        float* tE = (float*)(smem + PARAM_OFF + 1024);
        int col;
        if (MODE == 0) {
            int q2 = tid >> 4, rr = tid & 15, half = rr >> 3, jl = rr & 7;
            col = (half ? 256 : 0) + g * 128 + q2 * 8 + jl;
        } else {
            col = g * 256 + tid;
        }
        sE[tid] = bs[col];
        tE[tid] = bt[col];
    }

    float acc[16][4];
#pragma unroll
    for (int i = 0; i < 16; i++)
#pragma unroll
        for (int j = 0; j < 4; j++) acc[i][j] = 0.0f;

    const int nch = K >> 6;

    // per-thread load indices (fixed across chunks)
    const int rT = tid >> 3, cT = tid & 7;
    const uint32_t soA0 = (uint32_t)(rT * 128 + ((cT ^ (rT & 7)) << 4));
    const int rT1 = rT + 64;
    const uint32_t soA1 = (uint32_t)(rT1 * 128 + ((cT ^ (rT1 & 7)) << 4));
    const char* gAh = (const char*)(Ah + (size_t)(row0 + rT) * lda + cT * 8);
    const char* gAh1 = (const char*)(Ah + (size_t)(row0 + rT1) * lda + cT * 8);
    const char* gAl = (const char*)(Al + (size_t)(row0 + rT) * lda + cT * 8);
    const char* gAl1 = (const char*)(Al + (size_t)(row0 + rT1) * lda + cT * 8);
    const char* gB[4];
    uint32_t soB[4];
#pragma unroll
    for (int i = 0; i < 4; i++) {
        int r = rT + i * 64;
        soB[i] = (uint32_t)(32768 + r * 128 + ((cT ^ (r & 7)) << 4));
        gB[i] = (const char*)(B + (size_t)(g * 256 + r) * K + cT * 8);
    }

    auto load_stage = [&](int ch) {
        const uint32_t st = sb + (ch % 3) * STAGE_BYTES;
        const int kb = ch << 7;   // byte offset = ch*64 elems*2B
        cpa16(st + soA0,          gAh + kb);
        cpa16(st + soA1,          gAh1 + kb);
        cpa16(st + 16384 + soA0,  gAl + kb);
        cpa16(st + 16384 + soA1,  gAl1 + kb);
#pragma unroll
        for (int i = 0; i < 4; i++) cpa16(st + soB[i], gB[i] + kb);
    };

    load_stage(0);
    cpa_commit();
    if (nch > 1) { load_stage(1); cpa_commit(); }

    const int lr = lid & 15, lc = lid >> 4;
    // per-warp ldmatrix offsets within a stage (ks = 0)
    uint32_t offA[2], offB4[4];
#pragma unroll
    for (int m = 0; m < 2; m++) {
        int r = wm * 32 + m * 16 + lr;
        offA[m] = (uint32_t)(r * 128 + ((lc ^ (r & 7)) << 4));
    }
#pragma unroll
    for (int nb = 0; nb < 4; nb++) {
        int r = wn * 64 + nb * 16 + lr;
        offB4[nb] = (uint32_t)(32768 + r * 128 + ((lc ^ (r & 7)) << 4));
    }

    for (int ch = 0; ch < nch; ch++) {
        if (ch + 1 < nch) cpa_wait<1>(); else cpa_wait<0>();
        __syncthreads();
        if (ch + 2 < nch) { load_stage(ch + 2); cpa_commit(); }

        const uint32_t st = sb + (ch % 3) * STAGE_BYTES;
        uint32_t aH0 = st + offA[0], aH1 = st + offA[1];
        uint32_t aL0 = aH0 + 16384, aL1 = aH1 + 16384;
        uint32_t aB0 = st + offB4[0], aB1 = st + offB4[1];
        uint32_t aB2 = st + offB4[2], aB3 = st + offB4[3];

#pragma unroll
        for (int ks = 0; ks < 4; ks++) {
            uint32_t ah[2][4], al[2][4], bq[4][4];
            ldm4(ah[0], aH0); ldm4(ah[1], aH1);
            ldm4(al[0], aL0); ldm4(al[1], aL1);
            ldm4(bq[0], aB0); ldm4(bq[1], aB1);
            ldm4(bq[2], aB2); ldm4(bq[3], aB3);
#pragma unroll
            for (int nb = 0; nb < 4; nb++) {
#pragma unroll
                for (int m = 0; m < 2; m++) {
                    mma16(acc[m * 8 + 2 * nb],     ah[m], bq[nb][0], bq[nb][2]);
                    mma16(acc[m * 8 + 2 * nb + 1], ah[m], bq[nb][1], bq[nb][3]);
                    mma16(acc[m * 8 + 2 * nb],     al[m], bq[nb][0], bq[nb][2]);
                    mma16(acc[m * 8 + 2 * nb + 1], al[m], bq[nb][1], bq[nb][3]);
                }
            }
            const uint32_t d = (ks & 1) ? 96u : 32u;   // cc xor-delta << 4
            aH0 ^= d; aH1 ^= d; aL0 ^= d; aL1 ^= d;
            aB0 ^= d; aB1 ^= d; aB2 ^= d; aB3 ^= d;
        }
        __syncthreads();
    }

    // ---------------- epilogue ----------------
    const float* sE = (const float*)(smem + PARAM_OFF);
    const float* tE = (const float*)(smem + PARAM_OFF + 1024);
    const int gid = lid >> 2, tp = lid & 3;

    if (MODE == 0) {
#pragma unroll
        for (int m = 0; m < 2; m++) {
#pragma unroll
            for (int t = 0; t < 4; t++) {
                const int ja = wn * 64 + t * 16 + tp * 2;
                const int jb = ja + 8;
                const int cn = g * 128 + (wn * 4 + t) * 8 + tp * 2;
                const float sa0 = sE[ja], sa1 = sE[ja + 1];
                const float ta0 = tE[ja], ta1 = tE[ja + 1];
                const float sb0 = sE[jb], sb1 = sE[jb + 1];
                const float tb0 = tE[jb], tb1 = tE[jb + 1];
                const float* ca = acc[m * 8 + 2 * t];
                const float* cb = acc[m * 8 + 2 * t + 1];
#pragma unroll
                for (int h = 0; h < 2; h++) {
                    const int row = row0 + wm * 32 + m * 16 + gid + h * 8;
                    float xa0 = ca[2 * h] * sa0 + ta0;
                    float xa1 = ca[2 * h + 1] * sa1 + ta1;
                    float xb0 = cb[2 * h] * sb0 + tb0;
                    float xb1 = cb[2 * h + 1] * sb1 + tb1;
                    float o0 = xa0 * (1.0f / (1.0f + __expf(-xb0)));
                    float o1 = xa1 * (1.0f / (1.0f + __expf(-xb1)));
                    const size_t ob = (size_t)row * HS + cn;
                    if (resh) {
                        __half2 rh = *(const __half2*)(resh + ob);
                        __half2 rl = *(const __half2*)(resl + ob);
                        o0 = fmaf(__half2float(rh.x) + __half2float(rl.x),
                                  0.70710678118654752f, o0);
                        o1 = fmaf(__half2float(rh.y) + __half2float(rl.y),
                                  0.70710678118654752f, o1);
                    }
                    fp16 h0 = __float2half_rn(o0);
                    fp16 h1 = __float2half_rn(o1);
                    __half2 hh; hh.x = h0; hh.y = h1;
                    *(__half2*)(outh + ob) = hh;
                    __half2 ll;
                    ll.x = __float2half_rn(o0 - __half2float(h0));
                    ll.y = __float2half_rn(o1 - __half2float(h1));
                    *(__half2*)(outl + ob) = ll;
                    if (accp && g == 0) {
                        float2* ap = (float2*)(accp + (size_t)row * OUTD + cn);
                        float2 av = *ap;
                        av.x += fmaxf(o0, 0.0f);
                        av.y += fmaxf(o1, 0.0f);
                        *ap = av;
                    }
                }
            }
        }
    } else {
#pragma unroll
        for (int m = 0; m < 2; m++) {
#pragma unroll
            for (int nb2 = 0; nb2 < 8; nb2++) {
                const int cn = wn * 64 + nb2 * 8 + tp * 2;
                const float s0 = sE[cn], s1 = sE[cn + 1];
                const float t0 = tE[cn], t1 = tE[cn + 1];
                const float* ca = acc[m * 8 + nb2];
#pragma unroll
                for (int h = 0; h < 2; h++) {
                    const int row = row0 + wm * 32 + m * 16 + gid + h * 8;
                    const size_t idx = (size_t)row * FDIM + g * 256 + cn;
                    float2 pr = *(const float2*)(prior + idx);
                    float2 zz;
                    zz.x = (ca[2 * h] * s0 + t0) * pr.x;
                    zz.y = (ca[2 * h + 1] * s1 + t1) * pr.y;
                    *(float2*)(zout + idx) = zz;
                }
            }
        }
    }
}

// ---------------- sparsemax: one warp per row ----------------
__global__ __launch_bounds__(256)
void k_sparsemax(const float* __restrict__ z, float* __restrict__ prior,
                 float* __restrict__ maskOut,
                 fp16* __restrict__ mfh, fp16* __restrict__ mfl)
{
    const int row = blockIdx.x * 8 + (threadIdx.x >> 5);
    const int lid = threadIdx.x & 31;
    const size_t base = (size_t)row * 512;
    float v[16];
#pragma unroll
    for (int q = 0; q < 4; q++) {
        float4 t = *(const float4*)(z + base + q * 128 + lid * 4);
        v[q * 4 + 0] = t.x; v[q * 4 + 1] = t.y; v[q * 4 + 2] = t.z; v[q * 4 + 3] = t.w;
    }
    float zmax = v[0];
#pragma unroll
    for (int i = 1; i < 16; i++) zmax = fmaxf(zmax, v[i]);
#pragma unroll
    for (int o = 16; o; o >>= 1) zmax = fmaxf(zmax, __shfl_xor_sync(0xffffffffu, zmax, o));

    float lo = zmax - 1.0f, hi = zmax;
    for (int it = 0; it < 20; it++) {
        float mid = 0.5f * (lo + hi);
        float s = 0.0f;
#pragma unroll
        for (int i = 0; i < 16; i++) s += fmaxf(v[i] - mid, 0.0f);
#pragma unroll
        for (int o = 16; o; o >>= 1) s += __shfl_xor_sync(0xffffffffu, s, o);
        if (s >= 1.0f) lo = mid; else hi = mid;
    }
    float sum = 0.0f, cnt = 0.0f;
#pragma unroll
    for (int i = 0; i < 16; i++) {
        if (v[i] > lo) { sum += v[i]; cnt += 1.0f; }
    }
#pragma unroll
    for (int o = 16; o; o >>= 1) {
        sum += __shfl_xor_sync(0xffffffffu, sum, o);
        cnt += __shfl_xor_sync(0xffffffffu, cnt, o);
    }
    const float tau = (sum - 1.0f) / cnt;

#pragma unroll
    for (int q = 0; q < 4; q++) {
        const size_t off = base + q * 128 + lid * 4;
        float4 mk;
        mk.x = fmaxf(v[q * 4 + 0] - tau, 0.0f);
        mk.y = fmaxf(v[q * 4 + 1] - tau, 0.0f);
        mk.z = fmaxf(v[q * 4 + 2] - tau, 0.0f);
        mk.w = fmaxf(v[q * 4 + 3] - tau, 0.0f);
        *(float4*)(maskOut + off) = mk;
        float4 pr = *(const float4*)(prior + off);
        pr.x *= (1.5f - mk.x); pr.y *= (1.5f - mk.y);
        pr.z *= (1.5f - mk.z); pr.w *= (1.5f - mk.w);
        *(float4*)(prior + off) = pr;
        float4 ft = *(const float4*)(g_feats + off);
        float m0 = mk.x * ft.x, m1 = mk.y * ft.y, m2 = mk.z * ft.z, m3 = mk.w * ft.w;
        fp16 h0 = __float2half_rn(m0), h1 = __float2half_rn(m1);
        fp16 h2 = __float2half_rn(m2), h3 = __float2half_rn(m3);
        __half2 p0; p0.x = h0; p0.y = h1;
        __half2 p1; p1.x = h2; p1.y = h3;
        *(__half2*)(mfh + off) = p0;
        *(__half2*)(mfh + off + 2) = p1;
        __half2 q0, q1;
        q0.x = __float2half_rn(m0 - __half2float(h0));
        q0.y = __float2half_rn(m1 - __half2float(h1));
        q1.x = __float2half_rn(m2 - __half2float(h2));
        q1.y = __float2half_rn(m3 - __half2float(h3));
        *(__half2*)(mfl + off) = q0;
        *(__half2*)(mfl + off + 2) = q1;
    }
}

// ---------------- final projection ----------------
__global__ __launch_bounds__(256)
void k_fin(const float* __restrict__ A, const float* __restrict__ W,
           const float* __restrict__ bias, float* __restrict__ C)
{
    __shared__ float As[16][128];
    __shared__ float Ws[16][64];
    const int tid = threadIdx.x;
    const int ty = tid >> 4, tx = tid & 15;
    const int row0 = blockIdx.y * 128;
    const int col0 = blockIdx.x * 64;

    float acc[8][4];
#pragma unroll
    for (int r = 0; r < 8; r++)
#pragma unroll
        for (int c = 0; c < 4; c++) acc[r][c] = 0.f;

    for (int kt = 0; kt < 128; kt += 16) {
#pragma unroll
        for (int l = 0; l < 2; l++) {
            int li = tid * 2 + l;
            int r = li >> 2, kq = (li & 3) * 4;
            float4 av = *(const float4*)(A + (size_t)(row0 + r) * 128 + kt + kq);
            As[kq + 0][r] = av.x; As[kq + 1][r] = av.y;
            As[kq + 2][r] = av.z; As[kq + 3][r] = av.w;
        }
        *(float4*)&Ws[tid >> 4][(tid & 15) * 4] =
            *(const float4*)(W + (size_t)(kt + (tid >> 4)) * 128 + col0 + (tid & 15) * 4);
        __syncthreads();
#pragma unroll
        for (int kk = 0; kk < 16; kk++) {
            float a[8];
            float4 a0 = *(float4*)&As[kk][ty * 8];
            float4 a1 = *(float4*)&As[kk][ty * 8 + 4];
            a[0] = a0.x; a[1] = a0.y; a[2] = a0.z; a[3] = a0.w;
            a[4] = a1.x; a[5] = a1.y; a[6] = a1.z; a[7] = a1.w;
            float4 w0 = *(float4*)&Ws[kk][tx * 4];
            float wv[4] = {w0.x, w0.y, w0.z, w0.w};
#pragma unroll
            for (int r = 0; r < 8; r++)
#pragma unroll
                for (int c = 0; c < 4; c++) acc[r][c] += a[r] * wv[c];
        }
        __syncthreads();
    }
#pragma unroll
    for (int r = 0; r < 8; r++) {
        int gr = row0 + ty * 8 + r;
#pragma unroll
        for (int c = 0; c < 4; c++) {
            int gc = col0 + tx * 4 + c;
            C[(size_t)gr * 128 + gc] = acc[r][c] + bias[gc];
        }
    }
}

// ---------------- launch ----------------
extern "C" void kernel_launch(void* const* d_in, const int* in_sizes, int n_in,
                              void* d_out, int out_size)
{
    const float* features = (const float*)d_in[0];
    const float* bn0_g = (const float*)d_in[1];
    const float* bn0_b = (const float*)d_in[2];
    const float* bn0_m = (const float*)d_in[3];
    const float* bn0_v = (const float*)d_in[4];
    const float* Ws0   = (const float*)d_in[5];
    const float* Ws1   = (const float*)d_in[6];
    const float* Wu    = (const float*)d_in[7];
    const float* ft_g  = (const float*)d_in[8];
    const float* ft_b  = (const float*)d_in[9];
    const float* ft_m  = (const float*)d_in[10];
    const float* ft_v  = (const float*)d_in[11];
    const float* W_att = (const float*)d_in[12];
    const float* att_g = (const float*)d_in[13];
    const float* att_b = (const float*)d_in[14];
    const float* att_m = (const float*)d_in[15];
    const float* att_v = (const float*)d_in[16];
    const float* Wf    = (const float*)d_in[17];
    const float* bf    = (const float*)d_in[18];

    float *zp, *prior, *acc;
    fp16 *Ah, *Al, *h0h, *h0l, *h1h, *h1l;
    fp16 *W0, *W1, *WU, *WA;
    float *fts, *ftt, *as, *at;
    cudaGetSymbolAddress((void**)&Ah, g_Ah);
    cudaGetSymbolAddress((void**)&Al, g_Al);
    cudaGetSymbolAddress((void**)&h0h, g_h0h);
    cudaGetSymbolAddress((void**)&h0l, g_h0l);
    cudaGetSymbolAddress((void**)&h1h, g_h1h);
    cudaGetSymbolAddress((void**)&h1l, g_h1l);
    cudaGetSymbolAddress((void**)&zp, g_z);
    cudaGetSymbolAddress((void**)&prior, g_prior);
    cudaGetSymbolAddress((void**)&acc, g_acc);
    cudaGetSymbolAddress((void**)&W0, g_W0);
    cudaGetSymbolAddress((void**)&W1, g_W1);
    cudaGetSymbolAddress((void**)&WU, g_WU);
    cudaGetSymbolAddress((void**)&WA, g_WA);
    cudaGetSymbolAddress((void**)&fts, g_fts);
    cudaGetSymbolAddress((void**)&ftt, g_ftt);
    cudaGetSymbolAddress((void**)&as, g_as);
    cudaGetSymbolAddress((void**)&at, g_at);

    float* outF  = (float*)d_out;
    float* masks = outF + (size_t)BATCH * OUTD;

    static bool attr_set = false;
    if (!attr_set) {
        cudaFuncSetAttribute(k_mma<0>, cudaFuncAttributeMaxDynamicSharedMemorySize, SMEM_TOTAL);
        cudaFuncSetAttribute(k_mma<1>, cudaFuncAttributeMaxDynamicSharedMemorySize, SMEM_TOTAL);
        attr_set = true;
    }

    // ---- prep (2 launches) + init ----
    const int PREP_N = 512 * 512 + 512 * 256 + 12 * 512 * 256;
    k_prep_glu_all<<<(PREP_N + 255) / 256, 256>>>(Ws0, Ws1, Wu);
    k_prep_att_bn<<<(5 * 512 * 128 + 255) / 256, 256>>>(W_att, ft_g, ft_b, ft_m, ft_v,
                                                        att_g, att_b, att_m, att_v);
    k_init<<<(BATCH * FDIM) / 256, 256>>>(features, bn0_g, bn0_b, bn0_m, bn0_v);

    const dim3 gMma(2, BATCH / 128);

    auto ft_transformer = [&](int t, float* accOut) {
        const float* s0 = fts + (size_t)t * 4 * 512;
        const float* t0 = ftt + (size_t)t * 4 * 512;
        k_mma<0><<<gMma, 512, SMEM_TOTAL>>>(Ah, Al, 512, 512, W0,
            s0, t0, nullptr, nullptr, h0h, h0l, nullptr, nullptr, nullptr);
        k_mma<0><<<gMma, 512, SMEM_TOTAL>>>(h0h, h0l, 256, 256, W1,
            s0 + 512, t0 + 512, h0h, h0l, h1h, h1l, nullptr, nullptr, nullptr);
        k_mma<0><<<gMma, 512, SMEM_TOTAL>>>(h1h, h1l, 256, 256,
            WU + (size_t)(t * 2 + 0) * 512 * 256,
            s0 + 1024, t0 + 1024, h1h, h1l, h0h, h0l, nullptr, nullptr, nullptr);
        k_mma<0><<<gMma, 512, SMEM_TOTAL>>>(h0h, h0l, 256, 256,
            WU + (size_t)(t * 2 + 1) * 512 * 256,
            s0 + 1536, t0 + 1536, h0h, h0l, h1h, h1l, accOut, nullptr, nullptr);
    };

    ft_transformer(0, nullptr);

    for (int s = 0; s < STEPS; s++) {
        k_mma<1><<<gMma, 512, SMEM_TOTAL>>>(h1h + 128, h1l + 128, 256, 128,
            WA + (size_t)s * 512 * 128,
            as + (size_t)s * 512, at + (size_t)s * 512,
            nullptr, nullptr, nullptr, nullptr, nullptr,
            prior, zp);
        k_sparsemax<<<BATCH / 8, 256>>>(zp, prior, masks + (size_t)s * BATCH * FDIM, Ah, Al);
        ft_transformer(s + 1, acc);
    }

    k_fin<<<dim3(2, BATCH / 128), 256>>>(acc, Wf, bf, outF);
}